// round 8
// baseline (speedup 1.0000x reference)
#include <cuda_runtime.h>

#define SQ   512
#define BB   64
#define HH   512
#define NB   128     // persistent blocks (1/SM, all resident)
#define NT   256

typedef unsigned long long ull;

// Static device scratch (allocation-guard safe)
__device__ float g_c[(long long)SQ * BB * HH];   // fallback c-state history
__device__ int   g_flag[SQ * NB];                // per (step, block) ready flags

// ---------------- PTX helpers ----------------
__device__ __forceinline__ void ffma2(ull& d, ull a, ull b) {
    asm("fma.rn.f32x2 %0, %1, %2, %0;" : "+l"(d) : "l"(a), "l"(b));
}
__device__ __forceinline__ float2 unpackf2(ull v) {
    float2 r; asm("mov.b64 {%0, %1}, %2;" : "=f"(r.x), "=f"(r.y) : "l"(v)); return r;
}
__device__ __forceinline__ int ld_acq(const int* p) {
    int v; asm volatile("ld.acquire.gpu.global.s32 %0, [%1];" : "=r"(v) : "l"(p) : "memory");
    return v;
}
__device__ __forceinline__ void st_rel(int* p, int v) {
    asm volatile("st.release.gpu.global.s32 [%0], %1;" :: "l"(p), "r"(v) : "memory");
}
__device__ __forceinline__ float fex2(float x) {
    float r; asm("ex2.approx.ftz.f32 %0, %1;" : "=f"(r) : "f"(x)); return r;
}
__device__ __forceinline__ float frcp(float x) {
    float r; asm("rcp.approx.ftz.f32 %0, %1;" : "=f"(r) : "f"(x)); return r;
}
__device__ __forceinline__ float fsig(float x) {
    return frcp(1.0f + fex2(-1.4426950408889634f * x));
}
__device__ __forceinline__ float ftanh(float x) {
    return 1.0f - 2.0f * frcp(1.0f + fex2(2.8853900817779268f * x));
}

// ---------------- smem layout (all 16B-aligned strides) ----------------
// Weights: addr(nr, g, cl, q, kk) = nr*WNN + g*WROW + cl*144 + q*36 + kk
//   WROW=576 (2304B), WNN=4*576+8=2312 (9248B; 2312 mod 32 = 8)
//   Lane-varying: nn (stride 8 quads) x q (stride 4 quads... *36 mod 32 = 4)
//   -> 16 chunks over 8 quad-slots, 2-way -> 2-phase LDS (accepted).
// Chunk buffer: addr(b, q, kk) = b*HB + q*36 + kk, HB=148 (592B; 4*148 mod 32=16)
//   Lane-varying: bglow (16 quads) x q (4) -> 8 distinct -> 1-phase LDS.
#define WROW 576
#define WNN  2312
#define WARR 9248            // one weight matrix: 4 cols x 4 gates x 512 k (+pad)
#define HB   148
#define BUFW (64 * HB)       // 9472
#define SMEM_FLOATS (2 * WARR + 2 * BUFW)     // 37440
#define SMEM_BYTES  (SMEM_FLOATS * 4)         // 149760

// ---------------------------------------------------------------------------
__global__ void flag_init() {
    g_flag[blockIdx.x * NB + threadIdx.x] = 0;   // <<<SQ, NB>>>
}

// ---------------------------------------------------------------------------
// Fused persistent LSTM: per step, gates = [x_t ; h_(t-1)] . [w_ih ; w_hh]^T
// processed as 8 chunks of 128 k (0-3: x from seq[t]; 4-7: h from hout[t-1]).
// Block owns 4 h-columns. Thread (w, l): nn=l&3 (col), bglow=(l>>2)&1,
// q=l>>3 (k-quarter of each chunk); u=w*2+bglow; batches b0=4u..4u+3.
// Thread tile: 4 batches x 4 gates. K-quarter partials reduced via
// shfl.bfly(8) + shfl.bfly(16). c-state in registers.
// ---------------------------------------------------------------------------
__global__ __launch_bounds__(NT)
void lstm_fused(const float* __restrict__ seq,
                const float* __restrict__ wih,
                const float* __restrict__ whh,
                const float* __restrict__ bih,
                const float* __restrict__ bhh,
                float* __restrict__ hout,   // [S][B][H]  (hs output & h history)
                float* __restrict__ cout)   // [S][B][H]  (cs output)
{
    extern __shared__ __align__(16) float sm[];
    float* sWih  = sm;
    float* sWhh  = sm + WARR;
    float* sBuf0 = sm + 2 * WARR;
    float* sBuf1 = sBuf0 + BUFW;

    const int tid   = threadIdx.x;
    const int w     = tid >> 5;
    const int l     = tid & 31;
    const int nn    = l & 3;
    const int bglow = (l >> 2) & 1;
    const int q     = l >> 3;
    const int n0    = blockIdx.x * 4;
    const int u     = w * 2 + bglow;
    const int b0    = u * 4;
    const int n     = n0 + nn;

    // ---- Stage both weight matrices' 16 rows once ----
    #pragma unroll
    for (int i = 0; i < 8; i++) {
        int s  = tid + NT * i;             // 0..2047 float4 units
        int r  = s >> 7;
        int k4 = (s & 127) * 4;
        int nr = r >> 2, g = r & 3;
        int cl = k4 >> 7, qq = (k4 >> 5) & 3, kk = k4 & 31;
        int    doff = nr * WNN + g * WROW + cl * 144 + qq * 36 + kk;
        size_t soff = (size_t)(g * HH + n0 + nr) * HH + k4;
        *(float4*)(sWih + doff) = *(const float4*)(wih + soff);
        *(float4*)(sWhh + doff) = *(const float4*)(whh + soff);
    }

    // Per-thread gate biases
    float bias_[4];
    #pragma unroll
    for (int g = 0; g < 4; g++) bias_[g] = bih[g * HH + n] + bhh[g * HH + n];

    __syncthreads();

    float cr[4] = {0.f, 0.f, 0.f, 0.f};

    // Prefetch seq[0] chunk 0 into registers
    float4 pf[8];
    #pragma unroll
    for (int i = 0; i < 8; i++) {
        int s = tid + NT * i;              // 0..2047
        int b = s >> 5, k4 = (s & 31) * 4;
        pf[i] = *(const float4*)(seq + b * HH + k4);
    }

    for (int t = 0; t < SQ; t++) {
        // STS prefetched chunk 0 -> buf0
        #pragma unroll
        for (int i = 0; i < 8; i++) {
            int s = tid + NT * i;
            int b = s >> 5, k4 = (s & 31) * 4;
            *(float4*)(sBuf0 + b * HB + (k4 >> 5) * 36 + (k4 & 31)) = pf[i];
        }
        __syncthreads();

        ull a[4][4];
        #pragma unroll
        for (int bb = 0; bb < 4; bb++)
            #pragma unroll
            for (int g = 0; g < 4; g++) a[bb][g] = 0ULL;

        const int nch = (t == 0) ? 4 : 8;
        const float* xsrc = seq  + (size_t)t * BB * HH;
        const float* hsrc = hout + (size_t)(t - 1) * BB * HH;   // t==0: unused

        for (int c = 0; c < nch; c++) {
            const bool last = (c == nch - 1);

            // ---- Prefetch next chunk (LDG), overlapped with compute below ----
            if (!last) {
                if (c == 3) {
                    // About to read h(t-1): wait for all blocks' step t-1.
                    // (Only reachable when nch==8, i.e. t>0.)
                    if (tid < NB) {
                        while (ld_acq(&g_flag[(t - 1) * NB + tid]) == 0) {}
                    }
                    __syncthreads();
                }
                const int c1 = c + 1;
                const float* src = (c1 < 4 ? xsrc : hsrc) + (c1 & 3) * 128;
                #pragma unroll
                for (int i = 0; i < 8; i++) {
                    int s = tid + NT * i;
                    int b = s >> 5, k4 = (s & 31) * 4;
                    pf[i] = *(const float4*)(src + b * HH + k4);
                }
            } else if (t < SQ - 1) {
                // Last chunk of the step: prefetch seq[t+1] chunk 0
                const float* src = seq + (size_t)(t + 1) * BB * HH;
                #pragma unroll
                for (int i = 0; i < 8; i++) {
                    int s = tid + NT * i;
                    int b = s >> 5, k4 = (s & 31) * 4;
                    pf[i] = *(const float4*)(src + b * HH + k4);
                }
            }

            // ---- Compute chunk c: 32 k per thread, 4 batches x 4 gates ----
            const float* wa = (c < 4 ? sWih : sWhh) + nn * WNN + (c & 3) * 144 + q * 36;
            const float* hb = ((c & 1) ? sBuf1 : sBuf0) + b0 * HB + q * 36;
            #pragma unroll
            for (int kk = 0; kk < 32; kk += 4) {
                ulonglong2 w0 = *(const ulonglong2*)(wa + kk);
                ulonglong2 w1 = *(const ulonglong2*)(wa + WROW + kk);
                ulonglong2 w2 = *(const ulonglong2*)(wa + 2 * WROW + kk);
                ulonglong2 w3 = *(const ulonglong2*)(wa + 3 * WROW + kk);
                #pragma unroll
                for (int bb = 0; bb < 4; bb++) {
                    ulonglong2 hv = *(const ulonglong2*)(hb + bb * HB + kk);
                    ffma2(a[bb][0], hv.x, w0.x); ffma2(a[bb][0], hv.y, w0.y);
                    ffma2(a[bb][1], hv.x, w1.x); ffma2(a[bb][1], hv.y, w1.y);
                    ffma2(a[bb][2], hv.x, w2.x); ffma2(a[bb][2], hv.y, w2.y);
                    ffma2(a[bb][3], hv.x, w3.x); ffma2(a[bb][3], hv.y, w3.y);
                }
            }

            // ---- Store prefetched chunk into the other buffer ----
            if (!last) {
                float* db = (((c + 1) & 1) ? sBuf1 : sBuf0);
                #pragma unroll
                for (int i = 0; i < 8; i++) {
                    int s = tid + NT * i;
                    int b = s >> 5, k4 = (s & 31) * 4;
                    *(float4*)(db + b * HB + (k4 >> 5) * 36 + (k4 & 31)) = pf[i];
                }
                __syncthreads();
            }
        }

        // ---- Collapse f32x2 lanes + reduce K-quarters across lanes (q bits) ----
        float sg[4][4];
        #pragma unroll
        for (int bb = 0; bb < 4; bb++)
            #pragma unroll
            for (int g = 0; g < 4; g++) {
                float2 v = unpackf2(a[bb][g]);
                float x = v.x + v.y;
                x += __shfl_xor_sync(0xffffffffu, x, 8);
                x += __shfl_xor_sync(0xffffffffu, x, 16);
                sg[bb][g] = x;
            }

        // ---- Gate epilogue (order i, f, g, o); all lanes keep cr consistent ----
        float hn[4];
        #pragma unroll
        for (int bb = 0; bb < 4; bb++) {
            float pi = sg[bb][0] + bias_[0];
            float pF = sg[bb][1] + bias_[1];
            float pg = sg[bb][2] + bias_[2];
            float po = sg[bb][3] + bias_[3];
            float cn = fsig(pF) * cr[bb] + fsig(pi) * ftanh(pg);
            hn[bb] = fsig(po) * ftanh(cn);
            cr[bb] = cn;
        }

        // q==0 lanes store h, q==1 lanes store c (parallel, others idle)
        {
            size_t ob = (size_t)t * BB * HH + (size_t)b0 * HH + n;
            if (q == 0) {
                float* hO = hout + ob;
                hO[0] = hn[0]; hO[HH] = hn[1]; hO[2 * HH] = hn[2]; hO[3 * HH] = hn[3];
            } else if (q == 1) {
                float* cO = cout + ob;
                cO[0] = cr[0]; cO[HH] = cr[1]; cO[2 * HH] = cr[2]; cO[3 * HH] = cr[3];
            }
        }

        // Publish: bar orders all threads' stores before the release store.
        __syncthreads();
        if (tid == 0) st_rel(&g_flag[t * NB + blockIdx.x], 1);
    }
}

// ---------------------------------------------------------------------------
// Host
// ---------------------------------------------------------------------------
extern "C" void kernel_launch(void* const* d_in, const int* in_sizes, int n_in,
                              void* d_out, int out_size)
{
    const float* seq = (const float*)d_in[0];
    const float* wih = (const float*)d_in[1];
    const float* whh = (const float*)d_in[2];
    const float* bih = (const float*)d_in[3];
    const float* bhh = (const float*)d_in[4];
    float* out = (float*)d_out;

    float* cscr;
    cudaGetSymbolAddress((void**)&cscr, g_c);

    const size_t SBH = (size_t)SQ * BB * HH;
    float* cbase = ((size_t)out_size >= 2 * SBH) ? (out + SBH) : cscr;

    flag_init<<<SQ, NB>>>();

    cudaFuncSetAttribute(lstm_fused, cudaFuncAttributeMaxDynamicSharedMemorySize,
                         SMEM_BYTES);
    lstm_fused<<<NB, NT, SMEM_BYTES>>>(seq, wih, whh, bih, bhh, out, cbase);
}